// round 12
// baseline (speedup 1.0000x reference)
#include <cuda_runtime.h>
#include <cuda_fp16.h>
#include <cstdint>
#include <cstddef>

#define BB 2
#define TT 2048
#define CC 2048
#define HH 16
#define HD 128
#define TC3 6144   // 3*CC

// fp32 scratch (GEMM1 output)
__device__ float g_qkv[(size_t)BB * TT * TC3];

// fp16 split scratch
__device__ __half g_x_h[(size_t)BB * TT * CC];      // activations: single fp16
__device__ __half g_wa_h[(size_t)TC3 * CC];         // weights: 2-term
__device__ __half g_wa_l[(size_t)TC3 * CC];
__device__ __half g_wp_h[(size_t)CC * CC];
__device__ __half g_wp_l[(size_t)CC * CC];
__device__ __half g_y_h[(size_t)BB * TT * CC];      // attn out: single fp16

// attention operands
__device__ __half g_q_h[(size_t)BB * HH * TT * HD];  // Q single (pre-scaled)
__device__ __half g_k_h[(size_t)BB * HH * TT * HD];  // K 2-term
__device__ __half g_k_l[(size_t)BB * HH * TT * HD];
__device__ __half g_v_h[(size_t)BB * HH * HD * TT];  // V^T 2-term [b,h,d,t]
__device__ __half g_v_l[(size_t)BB * HH * HD * TT];

// ---------------------------------------------------------------------------
// helpers
// ---------------------------------------------------------------------------
__device__ __forceinline__ void cp16(void* smem_ptr, const void* gptr) {
    uint32_t s = (uint32_t)__cvta_generic_to_shared(smem_ptr);
    asm volatile("cp.async.ca.shared.global [%0], [%1], 16;\n" :: "r"(s), "l"(gptr));
}

__device__ __forceinline__ void mma16816(float* d, const uint32_t* a, const uint32_t* b) {
    asm volatile(
        "mma.sync.aligned.m16n8k16.row.col.f32.f16.f16.f32 "
        "{%0,%1,%2,%3}, {%4,%5,%6,%7}, {%8,%9}, {%0,%1,%2,%3};\n"
        : "+f"(d[0]), "+f"(d[1]), "+f"(d[2]), "+f"(d[3])
        : "r"(a[0]), "r"(a[1]), "r"(a[2]), "r"(a[3]), "r"(b[0]), "r"(b[1]));
}

// ---------------------------------------------------------------------------
// split kernels (unchanged from R11)
// ---------------------------------------------------------------------------
__global__ __launch_bounds__(256) void split1_kernel(const float* __restrict__ src,
                                                     __half* __restrict__ hi, int n) {
    int i = (blockIdx.x * blockDim.x + threadIdx.x) * 4;
    if (i >= n) return;
    float4 v = *(const float4*)(src + i);
    *(__half2*)(hi + i) = __floats2half2_rn(v.x, v.y);
    *(__half2*)(hi + i + 2) = __floats2half2_rn(v.z, v.w);
}

__global__ __launch_bounds__(256) void split2_kernel(const float* __restrict__ src,
                                                     __half* __restrict__ hi,
                                                     __half* __restrict__ lo, int n) {
    int i = (blockIdx.x * blockDim.x + threadIdx.x) * 4;
    if (i >= n) return;
    float4 v = *(const float4*)(src + i);
    __half h0 = __float2half_rn(v.x);
    __half h1 = __float2half_rn(v.y);
    __half h2 = __float2half_rn(v.z);
    __half h3 = __float2half_rn(v.w);
    __half2 hp0; hp0.x = h0; hp0.y = h1;
    __half2 hp1; hp1.x = h2; hp1.y = h3;
    __half2 lp0, lp1;
    lp0.x = __float2half_rn(v.x - __half2float(h0));
    lp0.y = __float2half_rn(v.y - __half2float(h1));
    lp1.x = __float2half_rn(v.z - __half2float(h2));
    lp1.y = __float2half_rn(v.w - __half2float(h3));
    *(__half2*)(hi + i) = hp0;
    *(__half2*)(hi + i + 2) = hp1;
    *(__half2*)(lo + i) = lp0;
    *(__half2*)(lo + i + 2) = lp1;
}

__global__ __launch_bounds__(256) void split_q1(const float* __restrict__ qkv,
                                                __half* __restrict__ hi, float scale) {
    int idx4 = (blockIdx.x * blockDim.x + threadIdx.x) * 4;
    int d = idx4 & 127;
    int t = (idx4 >> 7) & 2047;
    int bh = idx4 >> 18;
    int b = bh >> 4, h = bh & 15;
    const float* src = qkv + ((size_t)b * TT + t) * TC3 + h * HD + d;
    float4 v = *(const float4*)src;
    *(__half2*)(hi + idx4) = __floats2half2_rn(v.x * scale, v.y * scale);
    *(__half2*)(hi + idx4 + 2) = __floats2half2_rn(v.z * scale, v.w * scale);
}

__global__ __launch_bounds__(256) void split_k2(const float* __restrict__ qkv,
                                                __half* __restrict__ hi,
                                                __half* __restrict__ lo) {
    int idx4 = (blockIdx.x * blockDim.x + threadIdx.x) * 4;
    int d = idx4 & 127;
    int t = (idx4 >> 7) & 2047;
    int bh = idx4 >> 18;
    int b = bh >> 4, h = bh & 15;
    const float* src = qkv + ((size_t)b * TT + t) * TC3 + CC + h * HD + d;
    float4 v = *(const float4*)src;
    __half h0 = __float2half_rn(v.x);
    __half h1 = __float2half_rn(v.y);
    __half h2 = __float2half_rn(v.z);
    __half h3 = __float2half_rn(v.w);
    __half2 hp0; hp0.x = h0; hp0.y = h1;
    __half2 hp1; hp1.x = h2; hp1.y = h3;
    __half2 lp0, lp1;
    lp0.x = __float2half_rn(v.x - __half2float(h0));
    lp0.y = __float2half_rn(v.y - __half2float(h1));
    lp1.x = __float2half_rn(v.z - __half2float(h2));
    lp1.y = __float2half_rn(v.w - __half2float(h3));
    *(__half2*)(hi + idx4) = hp0;
    *(__half2*)(hi + idx4 + 2) = hp1;
    *(__half2*)(lo + idx4) = lp0;
    *(__half2*)(lo + idx4 + 2) = lp1;
}

__global__ __launch_bounds__(256) void split_v_T2(const float* __restrict__ qkv,
                                                  __half* __restrict__ hi,
                                                  __half* __restrict__ lo) {
    __shared__ float tile[32][33];
    int tx = threadIdx.x & 31;
    int ty = threadIdx.x >> 5;
    int t0 = blockIdx.x * 32;
    int d0 = blockIdx.y * 32;
    int bh = blockIdx.z;
    int b = bh >> 4, h = bh & 15;
#pragma unroll
    for (int i = 0; i < 4; ++i) {
        int t = t0 + ty + i * 8;
        tile[ty + i * 8][tx] = qkv[((size_t)b * TT + t) * TC3 + 2 * CC + h * HD + d0 + tx];
    }
    __syncthreads();
#pragma unroll
    for (int i = 0; i < 4; ++i) {
        int d = d0 + ty + i * 8;
        float v = tile[tx][ty + i * 8];
        __half hb = __float2half_rn(v);
        __half lb = __float2half_rn(v - __half2float(hb));
        size_t dst = ((size_t)bh * HD + d) * TT + t0 + tx;
        hi[dst] = hb;
        lo[dst] = lb;
    }
}

// ---------------------------------------------------------------------------
// fp16 2-product NT GEMM: C = A * (Bh + Bl)^T.
// 128x128x32 tile, 8 warps (2x4), 3-stage cp.async pipeline, single sync.
// ---------------------------------------------------------------------------
#define GBM 128
#define GBN 128
#define GBK 32
#define ASTRIDE 40
#define TILE_HALFS (128 * ASTRIDE)
#define TILE_BYTES (TILE_HALFS * 2)
#define GEMM_SMEM (3 * 3 * TILE_BYTES)   // 92160

__global__ __launch_bounds__(256, 2) void gemm_fp16split(
    const __half* __restrict__ Ah,
    const __half* __restrict__ Bh, const __half* __restrict__ Bl,
    float* __restrict__ Cg, int M, int N, int K) {
    extern __shared__ __half sm[];
    const int tid = threadIdx.x;
    const int lane = tid & 31;
    const int warp = tid >> 5;
    const int wm = warp >> 2;
    const int wn = warp & 3;
    const int bm = blockIdx.y * GBM;
    const int bn = blockIdx.x * GBN;

    float acc[4][4][4];
#pragma unroll
    for (int mt = 0; mt < 4; ++mt)
#pragma unroll
        for (int nt = 0; nt < 4; ++nt)
#pragma unroll
            for (int r = 0; r < 4; ++r) acc[mt][nt][r] = 0.f;

    const __half* gbase[3] = {Ah, Bh, Bl};

    auto load_stage = [&](int buf, int k0) {
#pragma unroll
        for (int arr = 0; arr < 3; ++arr) {
            int rowoff = (arr == 0) ? bm : bn;
            const __half* g = gbase[arr];
#pragma unroll
            for (int half = 0; half < 2; ++half) {
                int w = tid + half * 256;
                int row = w >> 2;
                int ck = (w & 3) * 8;
                cp16(&sm[(size_t)(buf * 3 + arr) * TILE_HALFS + row * ASTRIDE + ck],
                     g + (size_t)(rowoff + row) * K + k0 + ck);
            }
        }
    };

    const int nk = K / GBK;
    load_stage(0, 0);
    asm volatile("cp.async.commit_group;\n");
    load_stage(1, GBK);
    asm volatile("cp.async.commit_group;\n");

    int buf = 0, nxt = 2;
    for (int kt = 0; kt < nk; ++kt) {
        if (kt < nk - 1) {
            asm volatile("cp.async.wait_group 1;\n");   // stage kt resident
        } else {
            asm volatile("cp.async.wait_group 0;\n");
        }
        __syncthreads();   // stage kt visible to all; all warps done with stage kt-1
        if (kt + 2 < nk) {
            load_stage(nxt, (kt + 2) * GBK);            // overwrites stage kt-1 buffer
            asm volatile("cp.async.commit_group;\n");
        }

        const uint32_t* Ahs = (const uint32_t*)&sm[(size_t)(buf * 3 + 0) * TILE_HALFS];
        const uint32_t* Bhs = (const uint32_t*)&sm[(size_t)(buf * 3 + 1) * TILE_HALFS];
        const uint32_t* Bls = (const uint32_t*)&sm[(size_t)(buf * 3 + 2) * TILE_HALFS];

#pragma unroll
        for (int k16 = 0; k16 < 2; ++k16) {
            const int cA = k16 * 8 + (lane & 3);
            uint32_t bh[4][2], bl[4][2];
#pragma unroll
            for (int nt = 0; nt < 4; ++nt) {
                int nrow = wn * 32 + nt * 8 + (lane >> 2);
                bh[nt][0] = Bhs[nrow * 20 + cA];
                bh[nt][1] = Bhs[nrow * 20 + cA + 4];
                bl[nt][0] = Bls[nrow * 20 + cA];
                bl[nt][1] = Bls[nrow * 20 + cA + 4];
            }
#pragma unroll
            for (int mt = 0; mt < 4; ++mt) {
                int r = wm * 64 + mt * 16 + (lane >> 2);
                uint32_t ah[4];
                ah[0] = Ahs[r * 20 + cA];
                ah[1] = Ahs[(r + 8) * 20 + cA];
                ah[2] = Ahs[r * 20 + cA + 4];
                ah[3] = Ahs[(r + 8) * 20 + cA + 4];
#pragma unroll
                for (int nt = 0; nt < 4; ++nt) {
                    mma16816(acc[mt][nt], ah, bh[nt]);
                    mma16816(acc[mt][nt], ah, bl[nt]);
                }
            }
        }
        buf = (buf == 2) ? 0 : buf + 1;
        nxt = (nxt == 2) ? 0 : nxt + 1;
    }

#pragma unroll
    for (int mt = 0; mt < 4; ++mt) {
        int r = bm + wm * 64 + mt * 16 + (lane >> 2);
#pragma unroll
        for (int nt = 0; nt < 4; ++nt) {
            int c = bn + wn * 32 + nt * 8 + 2 * (lane & 3);
            *(float2*)&Cg[(size_t)r * N + c] = make_float2(acc[mt][nt][0], acc[mt][nt][1]);
            *(float2*)&Cg[(size_t)(r + 8) * N + c] = make_float2(acc[mt][nt][2], acc[mt][nt][3]);
        }
    }
}

// ---------------------------------------------------------------------------
// Tensor-core flash attention: Q/P single fp16, K/V 2-term.
// K/V double-buffered cp.async (R10-style single-boundary pipeline).
// ---------------------------------------------------------------------------
#define KBUF 17408
#define VBUF 18432
#define OFF_QH 0
#define OFF_KH 34816      // 2 x KBUF hi
#define OFF_KL 69632      // 2 x KBUF lo
#define OFF_VH 104448     // 2 x VBUF hi
#define OFF_VL 141312     // 2 x VBUF lo (note: 104448+36864=141312)
#define OFF_S  178176
#define OFF_PH 211456
#define OFF_M  228352
#define OFF_L  228864
#define OFF_AL 229376
#define ATTN_SMEM 229888
#define QSTR32 68
#define VSTR32 36
#define SSTRF  65
#define PSTR32 33

__global__ __launch_bounds__(256, 1) void attn_tc(
    const __half* __restrict__ qh,
    const __half* __restrict__ kh, const __half* __restrict__ kl,
    const __half* __restrict__ vh, const __half* __restrict__ vl,
    __half* __restrict__ yh) {
    extern __shared__ char smb[];
    __half* Qhs = (__half*)(smb + OFF_QH);
    float* Ss = (float*)(smb + OFF_S);
    __half* Phs = (__half*)(smb + OFF_PH);
    float* m_s = (float*)(smb + OFF_M);
    float* l_s = (float*)(smb + OFF_L);
    float* al_s = (float*)(smb + OFF_AL);

    const int tid = threadIdx.x;
    const int lane = tid & 31;
    const int warp = tid >> 5;
    const int wm = warp >> 1;
    const int wn = warp & 1;
    const int qb = 15 - (int)blockIdx.x;
    const int bh = blockIdx.y;
    const int b = bh >> 4;
    const int h = bh & 15;

    auto load_kv = [&](int buf, int kb) {
        const __half* ksh = kh + ((size_t)bh * TT + kb * 64) * HD;
        const __half* ksl = kl + ((size_t)bh * TT + kb * 64) * HD;
        char* kdh = smb + OFF_KH + buf * KBUF;
        char* kdl = smb + OFF_KL + buf * KBUF;
#pragma unroll
        for (int it = 0; it < 4; ++it) {
            int w = tid + it * 256;
            int row = w >> 4;
            int ck = (w & 15) * 8;
            cp16(kdh + (row * 136 + ck) * 2, ksh + (size_t)row * HD + ck);
            cp16(kdl + (row * 136 + ck) * 2, ksl + (size_t)row * HD + ck);
        }
        const __half* vsh = vh + (size_t)bh * HD * TT + kb * 64;
        const __half* vsl = vl + (size_t)bh * HD * TT + kb * 64;
        char* vdh = smb + OFF_VH + buf * VBUF;
        char* vdl = smb + OFF_VL + buf * VBUF;
#pragma unroll
        for (int it = 0; it < 4; ++it) {
            int w = tid + it * 256;
            int row = w >> 3;
            int ck = (w & 7) * 8;
            cp16(vdh + (row * 72 + ck) * 2, vsh + (size_t)row * TT + ck);
            cp16(vdl + (row * 72 + ck) * 2, vsl + (size_t)row * TT + ck);
        }
    };

    // prologue: Q + KV(0) in one group
    {
        const __half* qsh = qh + ((size_t)bh * TT + qb * 128) * HD;
#pragma unroll
        for (int it = 0; it < 8; ++it) {
            int w = tid + it * 256;
            int row = w >> 4;
            int ck = (w & 15) * 8;
            cp16(Qhs + row * 136 + ck, qsh + (size_t)row * HD + ck);
        }
        load_kv(0, 0);
        asm volatile("cp.async.commit_group;\n");
    }
    if (tid < 128) { m_s[tid] = -1e30f; l_s[tid] = 0.f; }

    float O[2][8][4];
#pragma unroll
    for (int mt = 0; mt < 2; ++mt)
#pragma unroll
        for (int nt = 0; nt < 8; ++nt)
#pragma unroll
            for (int r = 0; r < 4; ++r) O[mt][nt][r] = 0.f;

    const int nkb = 2 * qb + 2;
    for (int kb = 0; kb < nkb; ++kb) {
        const int buf = kb & 1;
        asm volatile("cp.async.wait_group 0;\n");   // KV(kb) (and Q) resident
        __syncthreads();                            // visible to all; prev PV done
        if (kb + 1 < nkb) {
            load_kv(buf ^ 1, kb + 1);               // overlaps S+softmax+PV below
            asm volatile("cp.async.commit_group;\n");
        }

        // ---- S = Q K^T (Q single, K 2-term) ----
        float sa[2][4][4];
#pragma unroll
        for (int mt = 0; mt < 2; ++mt)
#pragma unroll
            for (int nt = 0; nt < 4; ++nt)
#pragma unroll
                for (int r = 0; r < 4; ++r) sa[mt][nt][r] = 0.f;

        const uint32_t* Qh32 = (const uint32_t*)Qhs;
        const uint32_t* Kh32 = (const uint32_t*)(smb + OFF_KH + buf * KBUF);
        const uint32_t* Kl32 = (const uint32_t*)(smb + OFF_KL + buf * KBUF);
#pragma unroll
        for (int k16 = 0; k16 < 8; ++k16) {
            const int cA = k16 * 8 + (lane & 3);
            uint32_t bhf[4][2], blf[4][2];
#pragma unroll
            for (int nt = 0; nt < 4; ++nt) {
                int n = wn * 32 + nt * 8 + (lane >> 2);
                bhf[nt][0] = Kh32[n * QSTR32 + cA];
                bhf[nt][1] = Kh32[n * QSTR32 + cA + 4];
                blf[nt][0] = Kl32[n * QSTR32 + cA];
                blf[nt][1] = Kl32[n * QSTR32 + cA + 4];
            }
#pragma unroll
            for (int mt = 0; mt < 2; ++mt) {
                int r = wm * 32 + mt * 16 + (lane >> 2);
                uint32_t ah[4];
                ah[0] = Qh32[r * QSTR32 + cA];
                ah[1] = Qh32[(r + 8) * QSTR32 + cA];
                ah[2] = Qh32[r * QSTR32 + cA + 4];
                ah[3] = Qh32[(r + 8) * QSTR32 + cA + 4];
#pragma unroll
                for (int nt = 0; nt < 4; ++nt) {
                    mma16816(sa[mt][nt], ah, bhf[nt]);
                    mma16816(sa[mt][nt], ah, blf[nt]);
                }
            }
        }

#pragma unroll
        for (int mt = 0; mt < 2; ++mt) {
#pragma unroll
            for (int nt = 0; nt < 4; ++nt) {
                int rl = wm * 32 + mt * 16 + (lane >> 2);
                int cl = wn * 32 + nt * 8 + 2 * (lane & 3);
                int gr = qb * 128 + rl;
                int gc = kb * 64 + cl;
                float s0 = (gc > gr) ? -1e30f : sa[mt][nt][0];
                float s1 = (gc + 1 > gr) ? -1e30f : sa[mt][nt][1];
                float s2 = (gc > gr + 8) ? -1e30f : sa[mt][nt][2];
                float s3 = (gc + 1 > gr + 8) ? -1e30f : sa[mt][nt][3];
                Ss[rl * SSTRF + cl] = s0;
                Ss[rl * SSTRF + cl + 1] = s1;
                Ss[(rl + 8) * SSTRF + cl] = s2;
                Ss[(rl + 8) * SSTRF + cl + 1] = s3;
            }
        }
        __syncthreads();

        // ---- online softmax, P stored single fp16 ----
        if (tid < 128) {
            const int r = tid;
            const float* Sr = Ss + r * SSTRF;
            float mx = -1e30f;
#pragma unroll 8
            for (int c = 0; c < 64; ++c) mx = fmaxf(mx, Sr[c]);
            float mo = m_s[r];
            float mn = fmaxf(mo, mx);
            float alpha = __expf(mo - mn);
            float l = alpha * l_s[r];
            __half2* Pr_h = (__half2*)(Phs + r * 66);
#pragma unroll 4
            for (int c = 0; c < 64; c += 2) {
                float p0 = __expf(Sr[c] - mn);
                float p1 = __expf(Sr[c + 1] - mn);
                l += p0 + p1;
                Pr_h[c >> 1] = __floats2half2_rn(p0, p1);
            }
            m_s[r] = mn;
            l_s[r] = l;
            al_s[r] = alpha;
        }
        __syncthreads();

        // ---- O = O*alpha + P V (P single, V 2-term) ----
        {
            const uint32_t* Ph32 = (const uint32_t*)Phs;
            const uint32_t* Vh32 = (const uint32_t*)(smb + OFF_VH + buf * VBUF);
            const uint32_t* Vl32 = (const uint32_t*)(smb + OFF_VL + buf * VBUF);
#pragma unroll
            for (int mt = 0; mt < 2; ++mt) {
                int r = wm * 32 + mt * 16 + (lane >> 2);
                float aL = al_s[r];
                float aH = al_s[r + 8];
#pragma unroll
                for (int nt = 0; nt < 8; ++nt) {
                    O[mt][nt][0] *= aL; O[mt][nt][1] *= aL;
                    O[mt][nt][2] *= aH; O[mt][nt][3] *= aH;
                }
            }
#pragma unroll
            for (int k16 = 0; k16 < 4; ++k16) {
                const int cA = k16 * 8 + (lane & 3);
                uint32_t vbh[8][2], vbl[8][2];
#pragma unroll
                for (int nt = 0; nt < 8; ++nt) {
                    int n = wn * 64 + nt * 8 + (lane >> 2);
                    vbh[nt][0] = Vh32[n * VSTR32 + cA];
                    vbh[nt][1] = Vh32[n * VSTR32 + cA + 4];
                    vbl[nt][0] = Vl32[n * VSTR32 + cA];
                    vbl[nt][1] = Vl32[n * VSTR32 + cA + 4];
                }
#pragma unroll
                for (int mt = 0; mt < 2; ++mt) {
                    int r = wm * 32 + mt * 16 + (lane >> 2);
                    uint32_t pah[4];
                    pah[0] = Ph32[r * PSTR32 + cA];
                    pah[1] = Ph32[(r + 8) * PSTR32 + cA];
                    pah[2] = Ph32[r * PSTR32 + cA + 4];
                    pah[3] = Ph32[(r + 8) * PSTR32 + cA + 4];
#pragma unroll
                    for (int nt = 0; nt < 8; ++nt) {
                        mma16816(O[mt][nt], pah, vbh[nt]);
                        mma16816(O[mt][nt], pah, vbl[nt]);
                    }
                }
            }
        }
    }

    // ---- epilogue: normalize, emit y as single fp16 ----
#pragma unroll
    for (int mt = 0; mt < 2; ++mt) {
        int rl = wm * 32 + mt * 16 + (lane >> 2);
        float invL = 1.0f / l_s[rl];
        float invH = 1.0f / l_s[rl + 8];
#pragma unroll
        for (int nt = 0; nt < 8; ++nt) {
            int d = wn * 64 + nt * 8 + 2 * (lane & 3);
            int col = h * HD + d;
#pragma unroll
            for (int half = 0; half < 2; ++half) {
                int t = qb * 128 + rl + half * 8;
                float v0 = O[mt][nt][half * 2 + 0] * (half ? invH : invL);
                float v1 = O[mt][nt][half * 2 + 1] * (half ? invH : invL);
                size_t dst = ((size_t)b * TT + t) * CC + col;
                *(__half2*)(yh + dst) = __floats2half2_rn(v0, v1);
            }
        }
    }
}

// ---------------------------------------------------------------------------
extern "C" void kernel_launch(void* const* d_in, const int* in_sizes, int n_in,
                              void* d_out, int out_size) {
    const float* x = (const float*)d_in[0];
    const float* w_attn = (const float*)d_in[1];
    const float* w_proj = (const float*)d_in[2];
    float* out = (float*)d_out;

    float* qkv;
    __half *xh, *wah, *wal, *wph, *wpl, *yh;
    __half *aqh, *akh, *akl, *avh, *avl;
    cudaGetSymbolAddress((void**)&qkv, g_qkv);
    cudaGetSymbolAddress((void**)&xh, g_x_h);
    cudaGetSymbolAddress((void**)&wah, g_wa_h);
    cudaGetSymbolAddress((void**)&wal, g_wa_l);
    cudaGetSymbolAddress((void**)&wph, g_wp_h);
    cudaGetSymbolAddress((void**)&wpl, g_wp_l);
    cudaGetSymbolAddress((void**)&yh, g_y_h);
    cudaGetSymbolAddress((void**)&aqh, g_q_h);
    cudaGetSymbolAddress((void**)&akh, g_k_h);
    cudaGetSymbolAddress((void**)&akl, g_k_l);
    cudaGetSymbolAddress((void**)&avh, g_v_h);
    cudaGetSymbolAddress((void**)&avl, g_v_l);

    cudaFuncSetAttribute(gemm_fp16split, cudaFuncAttributeMaxDynamicSharedMemorySize, GEMM_SMEM);
    cudaFuncSetAttribute(attn_tc, cudaFuncAttributeMaxDynamicSharedMemorySize, ATTN_SMEM);

    const int nx = BB * TT * CC;
    const int nwa = TC3 * CC;
    const int nwp = CC * CC;
    const int nhd = BB * HH * TT * HD;

    split1_kernel<<<(nx / 4 + 255) / 256, 256>>>(x, xh, nx);
    split2_kernel<<<(nwa / 4 + 255) / 256, 256>>>(w_attn, wah, wal, nwa);
    split2_kernel<<<(nwp / 4 + 255) / 256, 256>>>(w_proj, wph, wpl, nwp);

    // 1) QKV projection: A = x (single), B = w_attn (2-term)
    gemm_fp16split<<<dim3(TC3 / GBN, (BB * TT) / GBM), 256, GEMM_SMEM>>>(
        xh, wah, wal, qkv, BB * TT, TC3, CC);

    // 2) split Q (single, scaled), K (2-term); split+transpose V (2-term)
    const float scale = 0.08838834764831845f;  // 1/sqrt(128)
    split_q1<<<nhd / 4 / 256, 256>>>(qkv, aqh, scale);
    split_k2<<<nhd / 4 / 256, 256>>>(qkv, akh, akl);
    split_v_T2<<<dim3(TT / 32, HD / 32, BB * HH), 256>>>(qkv, avh, avl);

    // 3) causal flash attention -> yh (single fp16)
    attn_tc<<<dim3(TT / 128, BB * HH), 256, ATTN_SMEM>>>(
        aqh, akh, akl, avh, avl, yh);

    // 4) output projection: A = y (single), B = w_proj (2-term)
    gemm_fp16split<<<dim3(CC / GBN, (BB * TT) / GBM), 256, GEMM_SMEM>>>(
        yh, wph, wpl, out, BB * TT, CC, CC);
}

// round 14
// speedup vs baseline: 1.0793x; 1.0793x over previous
#include <cuda_runtime.h>
#include <cuda_fp16.h>
#include <cstdint>
#include <cstddef>

#define BB 2
#define TT 2048
#define CC 2048
#define HH 16
#define HD 128
#define TC3 6144   // 3*CC

// fp32 scratch (GEMM1 output)
__device__ float g_qkv[(size_t)BB * TT * TC3];

// fp16 split scratch
__device__ __half g_x_h[(size_t)BB * TT * CC];      // activations: single fp16
__device__ __half g_wa_h[(size_t)TC3 * CC];         // weights: 2-term
__device__ __half g_wa_l[(size_t)TC3 * CC];
__device__ __half g_wp_h[(size_t)CC * CC];
__device__ __half g_wp_l[(size_t)CC * CC];
__device__ __half g_y_h[(size_t)BB * TT * CC];      // attn out: single fp16

// attention operands
__device__ __half g_q_h[(size_t)BB * HH * TT * HD];  // Q single (pre-scaled)
__device__ __half g_k_h[(size_t)BB * HH * TT * HD];  // K 2-term
__device__ __half g_k_l[(size_t)BB * HH * TT * HD];
__device__ __half g_v_h[(size_t)BB * HH * HD * TT];  // V^T 2-term [b,h,d,t]
__device__ __half g_v_l[(size_t)BB * HH * HD * TT];

// ---------------------------------------------------------------------------
// helpers
// ---------------------------------------------------------------------------
__device__ __forceinline__ void cp16(void* smem_ptr, const void* gptr) {
    uint32_t s = (uint32_t)__cvta_generic_to_shared(smem_ptr);
    asm volatile("cp.async.ca.shared.global [%0], [%1], 16;\n" :: "r"(s), "l"(gptr));
}

__device__ __forceinline__ void mma16816(float* d, const uint32_t* a, const uint32_t* b) {
    asm volatile(
        "mma.sync.aligned.m16n8k16.row.col.f32.f16.f16.f32 "
        "{%0,%1,%2,%3}, {%4,%5,%6,%7}, {%8,%9}, {%0,%1,%2,%3};\n"
        : "+f"(d[0]), "+f"(d[1]), "+f"(d[2]), "+f"(d[3])
        : "r"(a[0]), "r"(a[1]), "r"(a[2]), "r"(a[3]), "r"(b[0]), "r"(b[1]));
}

// ---------------------------------------------------------------------------
// split kernels (unchanged from R11)
// ---------------------------------------------------------------------------
__global__ __launch_bounds__(256) void split1_kernel(const float* __restrict__ src,
                                                     __half* __restrict__ hi, int n) {
    int i = (blockIdx.x * blockDim.x + threadIdx.x) * 4;
    if (i >= n) return;
    float4 v = *(const float4*)(src + i);
    *(__half2*)(hi + i) = __floats2half2_rn(v.x, v.y);
    *(__half2*)(hi + i + 2) = __floats2half2_rn(v.z, v.w);
}

__global__ __launch_bounds__(256) void split2_kernel(const float* __restrict__ src,
                                                     __half* __restrict__ hi,
                                                     __half* __restrict__ lo, int n) {
    int i = (blockIdx.x * blockDim.x + threadIdx.x) * 4;
    if (i >= n) return;
    float4 v = *(const float4*)(src + i);
    __half h0 = __float2half_rn(v.x);
    __half h1 = __float2half_rn(v.y);
    __half h2 = __float2half_rn(v.z);
    __half h3 = __float2half_rn(v.w);
    __half2 hp0; hp0.x = h0; hp0.y = h1;
    __half2 hp1; hp1.x = h2; hp1.y = h3;
    __half2 lp0, lp1;
    lp0.x = __float2half_rn(v.x - __half2float(h0));
    lp0.y = __float2half_rn(v.y - __half2float(h1));
    lp1.x = __float2half_rn(v.z - __half2float(h2));
    lp1.y = __float2half_rn(v.w - __half2float(h3));
    *(__half2*)(hi + i) = hp0;
    *(__half2*)(hi + i + 2) = hp1;
    *(__half2*)(lo + i) = lp0;
    *(__half2*)(lo + i + 2) = lp1;
}

__global__ __launch_bounds__(256) void split_q1(const float* __restrict__ qkv,
                                                __half* __restrict__ hi, float scale) {
    int idx4 = (blockIdx.x * blockDim.x + threadIdx.x) * 4;
    int d = idx4 & 127;
    int t = (idx4 >> 7) & 2047;
    int bh = idx4 >> 18;
    int b = bh >> 4, h = bh & 15;
    const float* src = qkv + ((size_t)b * TT + t) * TC3 + h * HD + d;
    float4 v = *(const float4*)src;
    *(__half2*)(hi + idx4) = __floats2half2_rn(v.x * scale, v.y * scale);
    *(__half2*)(hi + idx4 + 2) = __floats2half2_rn(v.z * scale, v.w * scale);
}

__global__ __launch_bounds__(256) void split_k2(const float* __restrict__ qkv,
                                                __half* __restrict__ hi,
                                                __half* __restrict__ lo) {
    int idx4 = (blockIdx.x * blockDim.x + threadIdx.x) * 4;
    int d = idx4 & 127;
    int t = (idx4 >> 7) & 2047;
    int bh = idx4 >> 18;
    int b = bh >> 4, h = bh & 15;
    const float* src = qkv + ((size_t)b * TT + t) * TC3 + CC + h * HD + d;
    float4 v = *(const float4*)src;
    __half h0 = __float2half_rn(v.x);
    __half h1 = __float2half_rn(v.y);
    __half h2 = __float2half_rn(v.z);
    __half h3 = __float2half_rn(v.w);
    __half2 hp0; hp0.x = h0; hp0.y = h1;
    __half2 hp1; hp1.x = h2; hp1.y = h3;
    __half2 lp0, lp1;
    lp0.x = __float2half_rn(v.x - __half2float(h0));
    lp0.y = __float2half_rn(v.y - __half2float(h1));
    lp1.x = __float2half_rn(v.z - __half2float(h2));
    lp1.y = __float2half_rn(v.w - __half2float(h3));
    *(__half2*)(hi + idx4) = hp0;
    *(__half2*)(hi + idx4 + 2) = hp1;
    *(__half2*)(lo + idx4) = lp0;
    *(__half2*)(lo + idx4 + 2) = lp1;
}

__global__ __launch_bounds__(256) void split_v_T2(const float* __restrict__ qkv,
                                                  __half* __restrict__ hi,
                                                  __half* __restrict__ lo) {
    __shared__ float tile[32][33];
    int tx = threadIdx.x & 31;
    int ty = threadIdx.x >> 5;
    int t0 = blockIdx.x * 32;
    int d0 = blockIdx.y * 32;
    int bh = blockIdx.z;
    int b = bh >> 4, h = bh & 15;
#pragma unroll
    for (int i = 0; i < 4; ++i) {
        int t = t0 + ty + i * 8;
        tile[ty + i * 8][tx] = qkv[((size_t)b * TT + t) * TC3 + 2 * CC + h * HD + d0 + tx];
    }
    __syncthreads();
#pragma unroll
    for (int i = 0; i < 4; ++i) {
        int d = d0 + ty + i * 8;
        float v = tile[tx][ty + i * 8];
        __half hb = __float2half_rn(v);
        __half lb = __float2half_rn(v - __half2float(hb));
        size_t dst = ((size_t)bh * HD + d) * TT + t0 + tx;
        hi[dst] = hb;
        lo[dst] = lb;
    }
}

// ---------------------------------------------------------------------------
// fp16 2-product NT GEMM: C = A * (Bh + Bl)^T.   (R11 exact: 2-stage pipeline)
// 128x128x32 tile, 8 warps (2x4), single-sync double-buffered cp.async.
// ---------------------------------------------------------------------------
#define GBM 128
#define GBN 128
#define GBK 32
#define ASTRIDE 40
#define TILE_HALFS (128 * ASTRIDE)
#define TILE_BYTES (TILE_HALFS * 2)
#define GEMM_SMEM (2 * 3 * TILE_BYTES)   // 61440

__global__ __launch_bounds__(256, 2) void gemm_fp16split(
    const __half* __restrict__ Ah,
    const __half* __restrict__ Bh, const __half* __restrict__ Bl,
    float* __restrict__ Cg, int M, int N, int K) {
    extern __shared__ __half sm[];
    const int tid = threadIdx.x;
    const int lane = tid & 31;
    const int warp = tid >> 5;
    const int wm = warp >> 2;
    const int wn = warp & 3;
    const int bm = blockIdx.y * GBM;
    const int bn = blockIdx.x * GBN;

    float acc[4][4][4];
#pragma unroll
    for (int mt = 0; mt < 4; ++mt)
#pragma unroll
        for (int nt = 0; nt < 4; ++nt)
#pragma unroll
            for (int r = 0; r < 4; ++r) acc[mt][nt][r] = 0.f;

    const __half* gbase[3] = {Ah, Bh, Bl};

    auto load_stage = [&](int buf, int k0) {
#pragma unroll
        for (int arr = 0; arr < 3; ++arr) {
            int rowoff = (arr == 0) ? bm : bn;
            const __half* g = gbase[arr];
#pragma unroll
            for (int half = 0; half < 2; ++half) {
                int w = tid + half * 256;
                int row = w >> 2;
                int ck = (w & 3) * 8;
                cp16(&sm[(size_t)(buf * 3 + arr) * TILE_HALFS + row * ASTRIDE + ck],
                     g + (size_t)(rowoff + row) * K + k0 + ck);
            }
        }
    };

    const int nk = K / GBK;
    load_stage(0, 0);
    asm volatile("cp.async.commit_group;\n");

    for (int kt = 0; kt < nk; ++kt) {
        const int buf = kt & 1;
        asm volatile("cp.async.wait_group 0;\n");
        __syncthreads();
        if (kt + 1 < nk) {
            load_stage(buf ^ 1, (kt + 1) * GBK);
            asm volatile("cp.async.commit_group;\n");
        }

        const uint32_t* Ahs = (const uint32_t*)&sm[(size_t)(buf * 3 + 0) * TILE_HALFS];
        const uint32_t* Bhs = (const uint32_t*)&sm[(size_t)(buf * 3 + 1) * TILE_HALFS];
        const uint32_t* Bls = (const uint32_t*)&sm[(size_t)(buf * 3 + 2) * TILE_HALFS];

#pragma unroll
        for (int k16 = 0; k16 < 2; ++k16) {
            const int cA = k16 * 8 + (lane & 3);
            uint32_t bh[4][2], bl[4][2];
#pragma unroll
            for (int nt = 0; nt < 4; ++nt) {
                int nrow = wn * 32 + nt * 8 + (lane >> 2);
                bh[nt][0] = Bhs[nrow * 20 + cA];
                bh[nt][1] = Bhs[nrow * 20 + cA + 4];
                bl[nt][0] = Bls[nrow * 20 + cA];
                bl[nt][1] = Bls[nrow * 20 + cA + 4];
            }
#pragma unroll
            for (int mt = 0; mt < 4; ++mt) {
                int r = wm * 64 + mt * 16 + (lane >> 2);
                uint32_t ah[4];
                ah[0] = Ahs[r * 20 + cA];
                ah[1] = Ahs[(r + 8) * 20 + cA];
                ah[2] = Ahs[r * 20 + cA + 4];
                ah[3] = Ahs[(r + 8) * 20 + cA + 4];
#pragma unroll
                for (int nt = 0; nt < 4; ++nt) {
                    mma16816(acc[mt][nt], ah, bh[nt]);
                    mma16816(acc[mt][nt], ah, bl[nt]);
                }
            }
        }
    }

#pragma unroll
    for (int mt = 0; mt < 4; ++mt) {
        int r = bm + wm * 64 + mt * 16 + (lane >> 2);
#pragma unroll
        for (int nt = 0; nt < 4; ++nt) {
            int c = bn + wn * 32 + nt * 8 + 2 * (lane & 3);
            *(float2*)&Cg[(size_t)r * N + c] = make_float2(acc[mt][nt][0], acc[mt][nt][1]);
            *(float2*)&Cg[(size_t)(r + 8) * N + c] = make_float2(acc[mt][nt][2], acc[mt][nt][3]);
        }
    }
}

// ---------------------------------------------------------------------------
// Tensor-core flash attention: Q/P single fp16, K/V 2-term.
// K/V double-buffered; softmax parallelized 2 threads/row (256 threads).
// ---------------------------------------------------------------------------
#define KBUF 17408
#define VBUF 18432
#define OFF_QH 0
#define OFF_KH 34816      // 2 x KBUF hi
#define OFF_KL 69632      // 2 x KBUF lo
#define OFF_VH 104448     // 2 x VBUF hi
#define OFF_VL 141312     // 2 x VBUF lo
#define OFF_S  178176
#define OFF_PH 211456
#define OFF_M  228352
#define OFF_L  228864
#define OFF_AL 229376
#define ATTN_SMEM 229888
#define QSTR32 68
#define VSTR32 36
#define SSTRF  65
#define PSTR32 33

__global__ __launch_bounds__(256, 1) void attn_tc(
    const __half* __restrict__ qh,
    const __half* __restrict__ kh, const __half* __restrict__ kl,
    const __half* __restrict__ vh, const __half* __restrict__ vl,
    __half* __restrict__ yh) {
    extern __shared__ char smb[];
    __half* Qhs = (__half*)(smb + OFF_QH);
    float* Ss = (float*)(smb + OFF_S);
    __half* Phs = (__half*)(smb + OFF_PH);
    float* m_s = (float*)(smb + OFF_M);
    float* l_s = (float*)(smb + OFF_L);
    float* al_s = (float*)(smb + OFF_AL);

    const int tid = threadIdx.x;
    const int lane = tid & 31;
    const int warp = tid >> 5;
    const int wm = warp >> 1;
    const int wn = warp & 1;
    const int qb = 15 - (int)blockIdx.x;
    const int bh = blockIdx.y;
    const int b = bh >> 4;
    const int h = bh & 15;

    auto load_kv = [&](int buf, int kb) {
        const __half* ksh = kh + ((size_t)bh * TT + kb * 64) * HD;
        const __half* ksl = kl + ((size_t)bh * TT + kb * 64) * HD;
        char* kdh = smb + OFF_KH + buf * KBUF;
        char* kdl = smb + OFF_KL + buf * KBUF;
#pragma unroll
        for (int it = 0; it < 4; ++it) {
            int w = tid + it * 256;
            int row = w >> 4;
            int ck = (w & 15) * 8;
            cp16(kdh + (row * 136 + ck) * 2, ksh + (size_t)row * HD + ck);
            cp16(kdl + (row * 136 + ck) * 2, ksl + (size_t)row * HD + ck);
        }
        const __half* vsh = vh + (size_t)bh * HD * TT + kb * 64;
        const __half* vsl = vl + (size_t)bh * HD * TT + kb * 64;
        char* vdh = smb + OFF_VH + buf * VBUF;
        char* vdl = smb + OFF_VL + buf * VBUF;
#pragma unroll
        for (int it = 0; it < 4; ++it) {
            int w = tid + it * 256;
            int row = w >> 3;
            int ck = (w & 7) * 8;
            cp16(vdh + (row * 72 + ck) * 2, vsh + (size_t)row * TT + ck);
            cp16(vdl + (row * 72 + ck) * 2, vsl + (size_t)row * TT + ck);
        }
    };

    // prologue: Q + KV(0) in one group
    {
        const __half* qsh = qh + ((size_t)bh * TT + qb * 128) * HD;
#pragma unroll
        for (int it = 0; it < 8; ++it) {
            int w = tid + it * 256;
            int row = w >> 4;
            int ck = (w & 15) * 8;
            cp16(Qhs + row * 136 + ck, qsh + (size_t)row * HD + ck);
        }
        load_kv(0, 0);
        asm volatile("cp.async.commit_group;\n");
    }
    if (tid < 128) { m_s[tid] = -1e30f; l_s[tid] = 0.f; }

    float O[2][8][4];
#pragma unroll
    for (int mt = 0; mt < 2; ++mt)
#pragma unroll
        for (int nt = 0; nt < 8; ++nt)
#pragma unroll
            for (int r = 0; r < 4; ++r) O[mt][nt][r] = 0.f;

    const int nkb = 2 * qb + 2;
    for (int kb = 0; kb < nkb; ++kb) {
        const int buf = kb & 1;
        asm volatile("cp.async.wait_group 0;\n");   // KV(kb) (and Q) resident
        __syncthreads();                            // visible to all; prev PV done
        if (kb + 1 < nkb) {
            load_kv(buf ^ 1, kb + 1);               // overlaps S+softmax+PV below
            asm volatile("cp.async.commit_group;\n");
        }

        // ---- S = Q K^T (Q single, K 2-term) ----
        float sa[2][4][4];
#pragma unroll
        for (int mt = 0; mt < 2; ++mt)
#pragma unroll
            for (int nt = 0; nt < 4; ++nt)
#pragma unroll
                for (int r = 0; r < 4; ++r) sa[mt][nt][r] = 0.f;

        const uint32_t* Qh32 = (const uint32_t*)Qhs;
        const uint32_t* Kh32 = (const uint32_t*)(smb + OFF_KH + buf * KBUF);
        const uint32_t* Kl32 = (const uint32_t*)(smb + OFF_KL + buf * KBUF);
#pragma unroll
        for (int k16 = 0; k16 < 8; ++k16) {
            const int cA = k16 * 8 + (lane & 3);
            uint32_t bhf[4][2], blf[4][2];
#pragma unroll
            for (int nt = 0; nt < 4; ++nt) {
                int n = wn * 32 + nt * 8 + (lane >> 2);
                bhf[nt][0] = Kh32[n * QSTR32 + cA];
                bhf[nt][1] = Kh32[n * QSTR32 + cA + 4];
                blf[nt][0] = Kl32[n * QSTR32 + cA];
                blf[nt][1] = Kl32[n * QSTR32 + cA + 4];
            }
#pragma unroll
            for (int mt = 0; mt < 2; ++mt) {
                int r = wm * 32 + mt * 16 + (lane >> 2);
                uint32_t ah[4];
                ah[0] = Qh32[r * QSTR32 + cA];
                ah[1] = Qh32[(r + 8) * QSTR32 + cA];
                ah[2] = Qh32[r * QSTR32 + cA + 4];
                ah[3] = Qh32[(r + 8) * QSTR32 + cA + 4];
#pragma unroll
                for (int nt = 0; nt < 4; ++nt) {
                    mma16816(sa[mt][nt], ah, bhf[nt]);
                    mma16816(sa[mt][nt], ah, blf[nt]);
                }
            }
        }

#pragma unroll
        for (int mt = 0; mt < 2; ++mt) {
#pragma unroll
            for (int nt = 0; nt < 4; ++nt) {
                int rl = wm * 32 + mt * 16 + (lane >> 2);
                int cl = wn * 32 + nt * 8 + 2 * (lane & 3);
                int gr = qb * 128 + rl;
                int gc = kb * 64 + cl;
                float s0 = (gc > gr) ? -1e30f : sa[mt][nt][0];
                float s1 = (gc + 1 > gr) ? -1e30f : sa[mt][nt][1];
                float s2 = (gc > gr + 8) ? -1e30f : sa[mt][nt][2];
                float s3 = (gc + 1 > gr + 8) ? -1e30f : sa[mt][nt][3];
                Ss[rl * SSTRF + cl] = s0;
                Ss[rl * SSTRF + cl + 1] = s1;
                Ss[(rl + 8) * SSTRF + cl] = s2;
                Ss[(rl + 8) * SSTRF + cl + 1] = s3;
            }
        }
        __syncthreads();

        // ---- online softmax: 2 threads per row, 32 cols each ----
        {
            const int r = tid >> 1;
            const int hf = tid & 1;
            const float* Sr = Ss + r * SSTRF + hf * 32;
            float mx = -1e30f;
#pragma unroll 8
            for (int c = 0; c < 32; ++c) mx = fmaxf(mx, Sr[c]);
            mx = fmaxf(mx, __shfl_xor_sync(0xffffffffu, mx, 1));
            float mo = m_s[r];
            float mn = fmaxf(mo, mx);
            float alpha = __expf(mo - mn);
            float s = 0.f;
            __half2* Pr_h = (__half2*)(Phs + r * 66 + hf * 32);
#pragma unroll 4
            for (int c = 0; c < 32; c += 2) {
                float p0 = __expf(Sr[c] - mn);
                float p1 = __expf(Sr[c + 1] - mn);
                s += p0 + p1;
                Pr_h[c >> 1] = __floats2half2_rn(p0, p1);
            }
            s += __shfl_xor_sync(0xffffffffu, s, 1);
            if (hf == 0) {
                m_s[r] = mn;
                l_s[r] = alpha * l_s[r] + s;
                al_s[r] = alpha;
            }
        }
        __syncthreads();

        // ---- O = O*alpha + P V (P single, V 2-term) ----
        {
            const uint32_t* Ph32 = (const uint32_t*)Phs;
            const uint32_t* Vh32 = (const uint32_t*)(smb + OFF_VH + buf * VBUF);
            const uint32_t* Vl32 = (const uint32_t*)(smb + OFF_VL + buf * VBUF);
#pragma unroll
            for (int mt = 0; mt < 2; ++mt) {
                int r = wm * 32 + mt * 16 + (lane >> 2);
                float aL = al_s[r];
                float aH = al_s[r + 8];
#pragma unroll
                for (int nt = 0; nt < 8; ++nt) {
                    O[mt][nt][0] *= aL; O[mt][nt][1] *= aL;
                    O[mt][nt][2] *= aH; O[mt][nt][3] *= aH;
                }
            }
#pragma unroll
            for (int k16 = 0; k16 < 4; ++k16) {
                const int cA = k16 * 8 + (lane & 3);
                uint32_t vbh[8][2], vbl[8][2];
#pragma unroll
                for (int nt = 0; nt < 8; ++nt) {
                    int n = wn * 64 + nt * 8 + (lane >> 2);
                    vbh[nt][0] = Vh32[n * VSTR32 + cA];
                    vbh[nt][1] = Vh32[n * VSTR32 + cA + 4];
                    vbl[nt][0] = Vl32[n * VSTR32 + cA];
                    vbl[nt][1] = Vl32[n * VSTR32 + cA + 4];
                }
#pragma unroll
                for (int mt = 0; mt < 2; ++mt) {
                    int r = wm * 32 + mt * 16 + (lane >> 2);
                    uint32_t pah[4];
                    pah[0] = Ph32[r * PSTR32 + cA];
                    pah[1] = Ph32[(r + 8) * PSTR32 + cA];
                    pah[2] = Ph32[r * PSTR32 + cA + 4];
                    pah[3] = Ph32[(r + 8) * PSTR32 + cA + 4];
#pragma unroll
                    for (int nt = 0; nt < 8; ++nt) {
                        mma16816(O[mt][nt], pah, vbh[nt]);
                        mma16816(O[mt][nt], pah, vbl[nt]);
                    }
                }
            }
        }
    }

    // ---- epilogue: normalize, emit y as single fp16 ----
#pragma unroll
    for (int mt = 0; mt < 2; ++mt) {
        int rl = wm * 32 + mt * 16 + (lane >> 2);
        float invL = 1.0f / l_s[rl];
        float invH = 1.0f / l_s[rl + 8];
#pragma unroll
        for (int nt = 0; nt < 8; ++nt) {
            int d = wn * 64 + nt * 8 + 2 * (lane & 3);
            int col = h * HD + d;
#pragma unroll
            for (int half = 0; half < 2; ++half) {
                int t = qb * 128 + rl + half * 8;
                float v0 = O[mt][nt][half * 2 + 0] * (half ? invH : invL);
                float v1 = O[mt][nt][half * 2 + 1] * (half ? invH : invL);
                size_t dst = ((size_t)b * TT + t) * CC + col;
                *(__half2*)(yh + dst) = __floats2half2_rn(v0, v1);
            }
        }
    }
}

// ---------------------------------------------------------------------------
extern "C" void kernel_launch(void* const* d_in, const int* in_sizes, int n_in,
                              void* d_out, int out_size) {
    const float* x = (const float*)d_in[0];
    const float* w_attn = (const float*)d_in[1];
    const float* w_proj = (const float*)d_in[2];
    float* out = (float*)d_out;

    float* qkv;
    __half *xh, *wah, *wal, *wph, *wpl, *yh;
    __half *aqh, *akh, *akl, *avh, *avl;
    cudaGetSymbolAddress((void**)&qkv, g_qkv);
    cudaGetSymbolAddress((void**)&xh, g_x_h);
    cudaGetSymbolAddress((void**)&wah, g_wa_h);
    cudaGetSymbolAddress((void**)&wal, g_wa_l);
    cudaGetSymbolAddress((void**)&wph, g_wp_h);
    cudaGetSymbolAddress((void**)&wpl, g_wp_l);
    cudaGetSymbolAddress((void**)&yh, g_y_h);
    cudaGetSymbolAddress((void**)&aqh, g_q_h);
    cudaGetSymbolAddress((void**)&akh, g_k_h);
    cudaGetSymbolAddress((void**)&akl, g_k_l);
    cudaGetSymbolAddress((void**)&avh, g_v_h);
    cudaGetSymbolAddress((void**)&avl, g_v_l);

    cudaFuncSetAttribute(gemm_fp16split, cudaFuncAttributeMaxDynamicSharedMemorySize, GEMM_SMEM);
    cudaFuncSetAttribute(attn_tc, cudaFuncAttributeMaxDynamicSharedMemorySize, ATTN_SMEM);

    const int nx = BB * TT * CC;
    const int nwa = TC3 * CC;
    const int nwp = CC * CC;
    const int nhd = BB * HH * TT * HD;

    split1_kernel<<<(nx / 4 + 255) / 256, 256>>>(x, xh, nx);
    split2_kernel<<<(nwa / 4 + 255) / 256, 256>>>(w_attn, wah, wal, nwa);
    split2_kernel<<<(nwp / 4 + 255) / 256, 256>>>(w_proj, wph, wpl, nwp);

    // 1) QKV projection: A = x (single), B = w_attn (2-term)
    gemm_fp16split<<<dim3(TC3 / GBN, (BB * TT) / GBM), 256, GEMM_SMEM>>>(
        xh, wah, wal, qkv, BB * TT, TC3, CC);

    // 2) split Q (single, scaled), K (2-term); split+transpose V (2-term)
    const float scale = 0.08838834764831845f;  // 1/sqrt(128)
    split_q1<<<nhd / 4 / 256, 256>>>(qkv, aqh, scale);
    split_k2<<<nhd / 4 / 256, 256>>>(qkv, akh, akl);
    split_v_T2<<<dim3(TT / 32, HD / 32, BB * HH), 256>>>(qkv, avh, avl);

    // 3) causal flash attention -> yh (single fp16)
    attn_tc<<<dim3(TT / 128, BB * HH), 256, ATTN_SMEM>>>(
        aqh, akh, akl, avh, avl, yh);

    // 4) output projection: A = y (single), B = w_proj (2-term)
    gemm_fp16split<<<dim3(CC / GBN, (BB * TT) / GBM), 256, GEMM_SMEM>>>(
        yh, wph, wpl, out, BB * TT, CC, CC);
}